// round 1
// baseline (speedup 1.0000x reference)
#include <cuda_runtime.h>
#include <math.h>

#define BATCH 2
#define TSEQ  2048
#define DM    1024
#define NH    16
#define DH    64
#define MTOT  (BATCH*TSEQ)   // 4096

// Scratch (device globals — no allocation allowed)
__device__ float g_q[(size_t)BATCH*NH*TSEQ*DH];    // [B*H, T, DH]
__device__ float g_k[(size_t)BATCH*NH*TSEQ*DH];
__device__ float g_v[(size_t)BATCH*NH*TSEQ*DH];
__device__ float g_ctx[(size_t)BATCH*TSEQ*DM];     // [B, T, D]

// ---------------------------------------------------------------------------
// C = A @ W^T.  A:[M,K] row-major, W:[N,K] row-major, M=4096, N=K=1024.
// MODE 0: scatter output into [B, H, T, DH] head-major layout (for q/k/v).
// MODE 1: plain [M, N] output + bias (final projection).
// 128x128 block tile, BK=16, 256 threads, 8x8 per-thread microtile.
// ---------------------------------------------------------------------------
template<int MODE>
__global__ void __launch_bounds__(256) gemm_xwt_kernel(
    const float* __restrict__ A, const float* __restrict__ W,
    const float* __restrict__ bias, float* __restrict__ C)
{
    __shared__ float AsT[16][132];   // [k][m], padded stride
    __shared__ float WsT[16][132];   // [k][n]

    const int tid = threadIdx.x;
    const int ty  = tid >> 4;        // 0..15
    const int tx  = tid & 15;        // 0..15
    const int m0  = blockIdx.y * 128;
    const int n0  = blockIdx.x * 128;

    float acc[8][8];
#pragma unroll
    for (int i = 0; i < 8; i++)
#pragma unroll
        for (int j = 0; j < 8; j++) acc[i][j] = 0.0f;

    for (int k0 = 0; k0 < DM; k0 += 16) {
        __syncthreads();
#pragma unroll
        for (int r = 0; r < 2; r++) {
            int id  = tid + 256 * r;          // 0..511
            int row = id >> 2;                // 0..127
            int kg  = (id & 3) * 4;           // 0,4,8,12
            float4 av = *(const float4*)(A + (size_t)(m0 + row) * DM + k0 + kg);
            AsT[kg+0][row] = av.x; AsT[kg+1][row] = av.y;
            AsT[kg+2][row] = av.z; AsT[kg+3][row] = av.w;
            float4 wv = *(const float4*)(W + (size_t)(n0 + row) * DM + k0 + kg);
            WsT[kg+0][row] = wv.x; WsT[kg+1][row] = wv.y;
            WsT[kg+2][row] = wv.z; WsT[kg+3][row] = wv.w;
        }
        __syncthreads();
#pragma unroll
        for (int k = 0; k < 16; k++) {
            float a[8], b[8];
            *(float4*)&a[0] = *(const float4*)&AsT[k][ty*8];
            *(float4*)&a[4] = *(const float4*)&AsT[k][ty*8+4];
            *(float4*)&b[0] = *(const float4*)&WsT[k][tx*8];
            *(float4*)&b[4] = *(const float4*)&WsT[k][tx*8+4];
#pragma unroll
            for (int i = 0; i < 8; i++)
#pragma unroll
                for (int j = 0; j < 8; j++)
                    acc[i][j] = fmaf(a[i], b[j], acc[i][j]);
        }
    }

    if (MODE == 0) {
        // n -> (h, dh); 8 consecutive n stay inside one head (8 | 64)
        const int nbase = n0 + tx * 8;
        const int h   = nbase >> 6;
        const int dh0 = nbase & 63;
#pragma unroll
        for (int i = 0; i < 8; i++) {
            int m  = m0 + ty * 8 + i;
            int bb = m >> 11;          // / TSEQ
            int t  = m & 2047;
            float* dst = C + ((size_t)(bb * NH + h) * TSEQ + t) * DH + dh0;
            *(float4*)(dst)     = make_float4(acc[i][0], acc[i][1], acc[i][2], acc[i][3]);
            *(float4*)(dst + 4) = make_float4(acc[i][4], acc[i][5], acc[i][6], acc[i][7]);
        }
    } else {
        float4 bv0 = *(const float4*)(bias + n0 + tx*8);
        float4 bv1 = *(const float4*)(bias + n0 + tx*8 + 4);
#pragma unroll
        for (int i = 0; i < 8; i++) {
            int m = m0 + ty * 8 + i;
            float* dst = C + (size_t)m * DM + n0 + tx * 8;
            *(float4*)(dst)     = make_float4(acc[i][0]+bv0.x, acc[i][1]+bv0.y,
                                              acc[i][2]+bv0.z, acc[i][3]+bv0.w);
            *(float4*)(dst + 4) = make_float4(acc[i][4]+bv1.x, acc[i][5]+bv1.y,
                                              acc[i][6]+bv1.z, acc[i][7]+bv1.w);
        }
    }
}

// ---------------------------------------------------------------------------
// Causal flash attention. Q,K,V: [B*H, T, DH]. One block = 64 queries of one
// (b,h). 256 threads in 16x16 layout, each owns a 4x4 fragment of S and O.
// Smem staged transposed (d-major) so both GEMMs read LDS.128 conflict-free.
// Softmax scale 1/8 is folded into the Q load.
// ---------------------------------------------------------------------------
#define ATTN_SMEM ((3*64*64 + 64*68) * 4)

__global__ void __launch_bounds__(256) attn_kernel(
    const float* __restrict__ Q, const float* __restrict__ K,
    const float* __restrict__ V, float* __restrict__ ctx)
{
    extern __shared__ float sm[];
    float* QsT = sm;                 // [d][q]  stride 64 (scaled by 1/8)
    float* KsT = QsT + 64*64;        // [d][n]  stride 64
    float* Vs  = KsT + 64*64;        // [n][d]  stride 64
    float* PsT = Vs  + 64*64;        // [n][q]  stride 68 (padded)

    const int tid = threadIdx.x;
    const int ty  = tid >> 4;        // query group 0..15
    const int tx  = tid & 15;        // col group   0..15
    const int qt  = blockIdx.x;      // 0..31
    const int bh  = blockIdx.y;      // 0..31
    const int b_  = bh >> 4;
    const int h   = bh & 15;

    const float* Qp = Q + ((size_t)bh * TSEQ + (size_t)qt * 64) * DH;
    const float* Kp = K + (size_t)bh * TSEQ * DH;
    const float* Vp = V + (size_t)bh * TSEQ * DH;

    // Load 64x64 Q tile transposed + scaled. Warp = 32 consecutive rows at one
    // d-group -> STS bank = row%32 -> conflict-free.
#pragma unroll
    for (int r = 0; r < 4; r++) {
        int id  = tid + 256 * r;     // 0..1023
        int row = id & 63;
        int dg  = (id >> 6) * 4;     // 0,4,...,60
        float4 v4 = *(const float4*)(Qp + (size_t)row * DH + dg);
        QsT[(dg+0)*64 + row] = v4.x * 0.125f;
        QsT[(dg+1)*64 + row] = v4.y * 0.125f;
        QsT[(dg+2)*64 + row] = v4.z * 0.125f;
        QsT[(dg+3)*64 + row] = v4.w * 0.125f;
    }

    float o[4][4];
    float m_i[4], l_i[4];
#pragma unroll
    for (int i = 0; i < 4; i++) {
        m_i[i] = -INFINITY; l_i[i] = 0.0f;
#pragma unroll
        for (int j = 0; j < 4; j++) o[i][j] = 0.0f;
    }

    const int ktiles = qt + 1;       // causal: only tiles at/below diagonal
    for (int kt = 0; kt < ktiles; kt++) {
        __syncthreads();             // prior-iter smem reads done
#pragma unroll
        for (int r = 0; r < 4; r++) {
            int id  = tid + 256 * r;
            int row = id & 63;
            int dg  = (id >> 6) * 4;
            float4 kv = *(const float4*)(Kp + ((size_t)kt*64 + row) * DH + dg);
            KsT[(dg+0)*64 + row] = kv.x;
            KsT[(dg+1)*64 + row] = kv.y;
            KsT[(dg+2)*64 + row] = kv.z;
            KsT[(dg+3)*64 + row] = kv.w;
            float4 vv = *(const float4*)(Vp + ((size_t)kt*64 + row) * DH + dg);
            *(float4*)&Vs[row*64 + dg] = vv;
        }
        __syncthreads();

        // S = (Q*scale) @ K^T   (64x64x64)
        float s[4][4];
#pragma unroll
        for (int i = 0; i < 4; i++)
#pragma unroll
            for (int j = 0; j < 4; j++) s[i][j] = 0.0f;
#pragma unroll
        for (int d = 0; d < 64; d++) {
            float a[4], bb[4];
            *(float4*)a  = *(const float4*)&QsT[d*64 + ty*4];
            *(float4*)bb = *(const float4*)&KsT[d*64 + tx*4];
#pragma unroll
            for (int i = 0; i < 4; i++)
#pragma unroll
                for (int j = 0; j < 4; j++)
                    s[i][j] = fmaf(a[i], bb[j], s[i][j]);
        }

        // Causal mask on the diagonal tile
        if (kt == qt) {
#pragma unroll
            for (int i = 0; i < 4; i++) {
                int qg = ty*4 + i;
#pragma unroll
                for (int j = 0; j < 4; j++)
                    if (tx*4 + j > qg) s[i][j] = -INFINITY;
            }
        }

        // Online softmax (row reduce across the 16 tx lanes via shfl)
#pragma unroll
        for (int i = 0; i < 4; i++) {
            float mx = fmaxf(fmaxf(s[i][0], s[i][1]), fmaxf(s[i][2], s[i][3]));
#pragma unroll
            for (int off = 1; off < 16; off <<= 1)
                mx = fmaxf(mx, __shfl_xor_sync(0xffffffffu, mx, off));
            float mnew  = fmaxf(m_i[i], mx);
            float alpha = __expf(m_i[i] - mnew);   // 0 on first tile (-inf)
            m_i[i] = mnew;
            float rs = 0.0f;
#pragma unroll
            for (int j = 0; j < 4; j++) {
                s[i][j] = __expf(s[i][j] - mnew);  // masked entries -> 0
                rs += s[i][j];
            }
#pragma unroll
            for (int off = 1; off < 16; off <<= 1)
                rs += __shfl_xor_sync(0xffffffffu, rs, off);
            l_i[i] = l_i[i] * alpha + rs;
#pragma unroll
            for (int j = 0; j < 4; j++) o[i][j] *= alpha;
        }

        // Stage P transposed: PsT[n][q], float4 along q
#pragma unroll
        for (int j = 0; j < 4; j++) {
            *(float4*)&PsT[(tx*4 + j)*68 + ty*4] =
                make_float4(s[0][j], s[1][j], s[2][j], s[3][j]);
        }
        __syncthreads();

        // O += P @ V   (64x64x64)
#pragma unroll
        for (int n = 0; n < 64; n++) {
            float a[4], bb[4];
            *(float4*)a  = *(const float4*)&PsT[n*68 + ty*4];
            *(float4*)bb = *(const float4*)&Vs[n*64 + tx*4];
#pragma unroll
            for (int i = 0; i < 4; i++)
#pragma unroll
                for (int j = 0; j < 4; j++)
                    o[i][j] = fmaf(a[i], bb[j], o[i][j]);
        }
    }

    // Normalize and write ctx in [B, T, D] layout (d = h*64 + dh)
#pragma unroll
    for (int i = 0; i < 4; i++) {
        float inv = 1.0f / l_i[i];
        int t = qt*64 + ty*4 + i;
        float* dst = g_ctx + ((size_t)(b_ * TSEQ + t)) * DM + h*64 + tx*4;
        *(float4*)dst = make_float4(o[i][0]*inv, o[i][1]*inv,
                                    o[i][2]*inv, o[i][3]*inv);
    }
}

// ---------------------------------------------------------------------------
extern "C" void kernel_launch(void* const* d_in, const int* in_sizes, int n_in,
                              void* d_out, int out_size)
{
    const float* x  = (const float*)d_in[0];
    const float* Wq = (const float*)d_in[1];
    const float* Wk = (const float*)d_in[2];
    const float* Wv = (const float*)d_in[3];
    const float* Wo = (const float*)d_in[4];
    const float* bo = (const float*)d_in[5];
    float* out = (float*)d_out;

    float *q, *k, *v, *ctx;
    cudaGetSymbolAddress((void**)&q,   g_q);
    cudaGetSymbolAddress((void**)&k,   g_k);
    cudaGetSymbolAddress((void**)&v,   g_v);
    cudaGetSymbolAddress((void**)&ctx, g_ctx);

    cudaFuncSetAttribute(attn_kernel,
                         cudaFuncAttributeMaxDynamicSharedMemorySize, ATTN_SMEM);

    dim3 ggrid(DM / 128, MTOT / 128);   // (8, 32)

    // NOTE the reference swaps names: q = x@Wk^T, k = x@Wq^T
    gemm_xwt_kernel<0><<<ggrid, 256>>>(x, Wk, nullptr, q);
    gemm_xwt_kernel<0><<<ggrid, 256>>>(x, Wq, nullptr, k);
    gemm_xwt_kernel<0><<<ggrid, 256>>>(x, Wv, nullptr, v);

    attn_kernel<<<dim3(TSEQ/64, BATCH*NH), 256, ATTN_SMEM>>>(q, k, v, ctx);

    gemm_xwt_kernel<1><<<ggrid, 256>>>(ctx, Wo, bo, out);
}

// round 3
// speedup vs baseline: 2.4538x; 2.4538x over previous
#include <cuda_runtime.h>
#include <cuda_bf16.h>
#include <math.h>
#include <stdint.h>

#define BATCH 2
#define TSEQ  2048
#define DM    1024
#define NH    16
#define DH    64
#define MTOT  (BATCH*TSEQ)   // 4096

// ---------------- scratch (device globals; no allocation allowed) ----------
__device__ __align__(16) float g_q[(size_t)BATCH*NH*TSEQ*DH];
__device__ __align__(16) float g_k[(size_t)BATCH*NH*TSEQ*DH];
__device__ __align__(16) float g_v[(size_t)BATCH*NH*TSEQ*DH];
__device__ __align__(16) float g_ctx[(size_t)BATCH*TSEQ*DM];

__device__ __align__(16) __nv_bfloat16 g_xh[(size_t)MTOT*DM];
__device__ __align__(16) __nv_bfloat16 g_xl[(size_t)MTOT*DM];
__device__ __align__(16) __nv_bfloat16 g_wh[(size_t)3*DM*DM];  // [Wk;Wq;Wv] (q<-Wk swap!)
__device__ __align__(16) __nv_bfloat16 g_wl[(size_t)3*DM*DM];
__device__ __align__(16) __nv_bfloat16 g_ch[(size_t)MTOT*DM];
__device__ __align__(16) __nv_bfloat16 g_cl[(size_t)MTOT*DM];
__device__ __align__(16) __nv_bfloat16 g_woh[(size_t)DM*DM];
__device__ __align__(16) __nv_bfloat16 g_wol[(size_t)DM*DM];

// ---------------- helpers ---------------------------------------------------
__device__ __forceinline__ uint32_t smem_u32(const void* p) {
    uint32_t a;
    asm("{ .reg .u64 t; cvta.to.shared.u64 t, %1; cvt.u32.u64 %0, t; }"
        : "=r"(a) : "l"(p));
    return a;
}
__device__ __forceinline__ void cp_async16(uint32_t dst, const void* src) {
    asm volatile("cp.async.cg.shared.global [%0], [%1], 16;"
                 :: "r"(dst), "l"(src) : "memory");
}
__device__ __forceinline__ void cp_commit() {
    asm volatile("cp.async.commit_group;" ::: "memory");
}
__device__ __forceinline__ void cp_wait_all() {
    asm volatile("cp.async.wait_group 0;" ::: "memory");
}
__device__ __forceinline__ void ldsm4(uint32_t* r, uint32_t a) {
    asm volatile("ldmatrix.sync.aligned.m8n8.x4.shared.b16 {%0,%1,%2,%3}, [%4];"
                 : "=r"(r[0]), "=r"(r[1]), "=r"(r[2]), "=r"(r[3]) : "r"(a));
}
__device__ __forceinline__ void mma_bf16(float* c, const uint32_t* a, const uint32_t* b) {
    asm volatile(
        "mma.sync.aligned.m16n8k16.row.col.f32.bf16.bf16.f32 "
        "{%0,%1,%2,%3}, {%4,%5,%6,%7}, {%8,%9}, {%0,%1,%2,%3};"
        : "+f"(c[0]), "+f"(c[1]), "+f"(c[2]), "+f"(c[3])
        : "r"(a[0]), "r"(a[1]), "r"(a[2]), "r"(a[3]), "r"(b[0]), "r"(b[1]));
}
// SW128 swizzle on (row,colb): row stride 128B
__device__ __forceinline__ uint32_t swz(int row, int colb) {
    uint32_t off = row * 128 + colb;
    return off ^ ((off >> 3) & 0x70);
}

// ---------------- fp32 -> bf16 hi/lo split ----------------------------------
__global__ void __launch_bounds__(256) split_kernel(
    const float* __restrict__ in, __nv_bfloat16* __restrict__ hi,
    __nv_bfloat16* __restrict__ lo, int n4)
{
    int i = blockIdx.x * 256 + threadIdx.x;
    if (i >= n4) return;
    float4 v = ((const float4*)in)[i];
    __nv_bfloat16 h[4], l[4];
    float f[4] = {v.x, v.y, v.z, v.w};
#pragma unroll
    for (int j = 0; j < 4; j++) {
        h[j] = __float2bfloat16(f[j]);
        l[j] = __float2bfloat16(f[j] - __bfloat162float(h[j]));
    }
    *(uint2*)(hi + (size_t)i*4) = *(uint2*)h;
    *(uint2*)(lo + (size_t)i*4) = *(uint2*)l;
}

// ---------------------------------------------------------------------------
// Split-bf16 GEMM on HMMA (mma.sync m16n8k16):
//   C[M,N] = (Ah+Al)[M,K] @ (Bh+Bl)[N,K]^T   keeping hh + hl + lh
// 128x128 block tile, BK=64, double-buffered cp.async smem, 256 threads.
// Warp w: rows (w&3)*32..+31, cols (w>>2)*64..+63 -> 2 x 8 m16n8 fragments.
// MODE 0: scatter into q/k/v head-major (fused QKV, N=3072)
// MODE 1: out[m*DM+n] + bias
// ---------------------------------------------------------------------------
#define GK       DM
#define BK       64
#define NCHUNK   (GK/BK)        // 16
#define TILE_B   (128*128)      // 128 rows * 128B (64 bf16)
#define BUF_B    (4*TILE_B)     // Ah, Al, Bh, Bl
#define GEMM_SMEM (2*BUF_B)     // 131072

template<int MODE>
__global__ void __launch_bounds__(256, 1) mma_gemm(
    const __nv_bfloat16* __restrict__ Ah, const __nv_bfloat16* __restrict__ Al,
    const __nv_bfloat16* __restrict__ Bh, const __nv_bfloat16* __restrict__ Bl,
    float* __restrict__ q, float* __restrict__ k, float* __restrict__ v,
    float* __restrict__ out, const float* __restrict__ bias)
{
    extern __shared__ char smem[];
    const uint32_t sb = smem_u32(smem);
    const int tid  = threadIdx.x;
    const int lane = tid & 31;
    const int w    = tid >> 5;
    const int m0   = blockIdx.y * 128;
    const int n0   = blockIdx.x * 128;

    const __nv_bfloat16* srcs[4] = {Ah + (size_t)m0*GK, Al + (size_t)m0*GK,
                                    Bh + (size_t)n0*GK, Bl + (size_t)n0*GK};

    auto issue_chunk = [&](int buf, int k0) {
        uint32_t dbase = sb + buf * BUF_B;
#pragma unroll
        for (int t = 0; t < 4; t++) {
            const __nv_bfloat16* src = srcs[t] + k0;
            uint32_t tb = dbase + t * TILE_B;
#pragma unroll
            for (int r2 = 0; r2 < 4; r2++) {
                int id  = tid + 256 * r2;
                int row = id >> 3;
                int c16 = id & 7;
                cp_async16(tb + swz(row, c16 * 16), src + (size_t)row*GK + c16*8);
            }
        }
        cp_commit();
    };

    float acc[2][8][4];
#pragma unroll
    for (int mt = 0; mt < 2; mt++)
#pragma unroll
        for (int nt = 0; nt < 8; nt++)
#pragma unroll
            for (int e = 0; e < 4; e++) acc[mt][nt][e] = 0.0f;

    const int mr  = (w & 3) * 32;
    const int nc0 = (w >> 2) * 64;
    const int quad = lane >> 3;
    const int l7   = lane & 7;
    // per-lane ldmatrix row/col offsets
    const int a_row_off = (quad & 1) * 8 + l7;     // within m16 tile
    const int a_col_off = (quad >> 1) * 16;        // bytes within k16
    const int b_row_off = (quad >> 1) * 8 + l7;    // within n16 group
    const int b_col_off = (quad & 1) * 16;

    issue_chunk(0, 0);

    for (int c = 0; c < NCHUNK; c++) {
        const int b = c & 1;
        cp_wait_all();
        __syncthreads();
        if (c + 1 < NCHUNK) issue_chunk(b ^ 1, (c + 1) * BK);

        const uint32_t pAh = sb + b*BUF_B;
        const uint32_t pAl = pAh + TILE_B;
        const uint32_t pBh = pAh + 2*TILE_B;
        const uint32_t pBl = pAh + 3*TILE_B;

#pragma unroll
        for (int ks = 0; ks < 4; ks++) {
            const int k0b = ks * 32;     // bytes
            uint32_t aH[2][4], aL[2][4], bF[8][2];
#pragma unroll
            for (int mt = 0; mt < 2; mt++) {
                int row = mr + mt*16 + a_row_off;
                ldsm4(aH[mt], pAh + swz(row, k0b + a_col_off));
                ldsm4(aL[mt], pAl + swz(row, k0b + a_col_off));
            }
            // B hi
#pragma unroll
            for (int ng = 0; ng < 4; ng++) {
                uint32_t t4[4];
                ldsm4(t4, pBh + swz(nc0 + ng*16 + b_row_off, k0b + b_col_off));
                bF[ng*2][0] = t4[0]; bF[ng*2][1] = t4[1];
                bF[ng*2+1][0] = t4[2]; bF[ng*2+1][1] = t4[3];
            }
#pragma unroll
            for (int mt = 0; mt < 2; mt++)
#pragma unroll
                for (int nt = 0; nt < 8; nt++) {
                    mma_bf16(acc[mt][nt], aH[mt], bF[nt]);   // hh
                }
#pragma unroll
            for (int mt = 0; mt < 2; mt++)
#pragma unroll
                for (int nt = 0; nt < 8; nt++) {
                    mma_bf16(acc[mt][nt], aL[mt], bF[nt]);   // lh
                }
            // B lo (reuse bF regs)
#pragma unroll
            for (int ng = 0; ng < 4; ng++) {
                uint32_t t4[4];
                ldsm4(t4, pBl + swz(nc0 + ng*16 + b_row_off, k0b + b_col_off));
                bF[ng*2][0] = t4[0]; bF[ng*2][1] = t4[1];
                bF[ng*2+1][0] = t4[2]; bF[ng*2+1][1] = t4[3];
            }
#pragma unroll
            for (int mt = 0; mt < 2; mt++)
#pragma unroll
                for (int nt = 0; nt < 8; nt++) {
                    mma_bf16(acc[mt][nt], aH[mt], bF[nt]);   // hl
                }
        }
        __syncthreads();
    }

    // ---- epilogue: direct register writeback ----
#pragma unroll
    for (int mt = 0; mt < 2; mt++) {
#pragma unroll
        for (int half = 0; half < 2; half++) {
            const int m = m0 + mr + mt*16 + (lane >> 2) + half*8;
#pragma unroll
            for (int nt = 0; nt < 8; nt++) {
                const int n = n0 + nc0 + nt*8 + (lane & 3)*2;
                const float c0 = acc[mt][nt][half*2 + 0];
                const float c1 = acc[mt][nt][half*2 + 1];
                if (MODE == 0) {
                    const int bb  = m >> 11;
                    const int t   = m & 2047;
                    const int mat = n >> 10;
                    const int np  = n & 1023;
                    float* dst = (mat == 0) ? q : ((mat == 1) ? k : v);
                    float* p = dst + ((size_t)(bb*NH + (np >> 6)) * TSEQ + t) * DH + (np & 63);
                    p[0] = c0; p[1] = c1;
                } else {
                    float* p = out + (size_t)m * DM + n;
                    p[0] = c0 + __ldg(bias + n);
                    p[1] = c1 + __ldg(bias + n + 1);
                }
            }
        }
    }
}

// ---------------------------------------------------------------------------
// Causal flash attention (fp32) — unchanged from the passing round-1 kernel.
// ---------------------------------------------------------------------------
#define ATTN_SMEM ((3*64*64 + 64*68) * 4)

__global__ void __launch_bounds__(256) attn_kernel(
    const float* __restrict__ Q, const float* __restrict__ K,
    const float* __restrict__ V, float* __restrict__ ctx)
{
    extern __shared__ float sm[];
    float* QsT = sm;
    float* KsT = QsT + 64*64;
    float* Vs  = KsT + 64*64;
    float* PsT = Vs  + 64*64;

    const int tid = threadIdx.x;
    const int ty  = tid >> 4;
    const int tx  = tid & 15;
    const int qt  = blockIdx.x;
    const int bh  = blockIdx.y;
    const int b_  = bh >> 4;
    const int h   = bh & 15;

    const float* Qp = Q + ((size_t)bh * TSEQ + (size_t)qt * 64) * DH;
    const float* Kp = K + (size_t)bh * TSEQ * DH;
    const float* Vp = V + (size_t)bh * TSEQ * DH;

#pragma unroll
    for (int r = 0; r < 4; r++) {
        int id  = tid + 256 * r;
        int row = id & 63;
        int dg  = (id >> 6) * 4;
        float4 v4 = *(const float4*)(Qp + (size_t)row * DH + dg);
        QsT[(dg+0)*64 + row] = v4.x * 0.125f;
        QsT[(dg+1)*64 + row] = v4.y * 0.125f;
        QsT[(dg+2)*64 + row] = v4.z * 0.125f;
        QsT[(dg+3)*64 + row] = v4.w * 0.125f;
    }

    float o[4][4];
    float m_i[4], l_i[4];
#pragma unroll
    for (int i = 0; i < 4; i++) {
        m_i[i] = -INFINITY; l_i[i] = 0.0f;
#pragma unroll
        for (int j = 0; j < 4; j++) o[i][j] = 0.0f;
    }

    const int ktiles = qt + 1;
    for (int kt = 0; kt < ktiles; kt++) {
        __syncthreads();
#pragma unroll
        for (int r = 0; r < 4; r++) {
            int id  = tid + 256 * r;
            int row = id & 63;
            int dg  = (id >> 6) * 4;
            float4 kv = *(const float4*)(Kp + ((size_t)kt*64 + row) * DH + dg);
            KsT[(dg+0)*64 + row] = kv.x;
            KsT[(dg+1)*64 + row] = kv.y;
            KsT[(dg+2)*64 + row] = kv.z;
            KsT[(dg+3)*64 + row] = kv.w;
            float4 vv = *(const float4*)(Vp + ((size_t)kt*64 + row) * DH + dg);
            *(float4*)&Vs[row*64 + dg] = vv;
        }
        __syncthreads();

        float s[4][4];
#pragma unroll
        for (int i = 0; i < 4; i++)
#pragma unroll
            for (int j = 0; j < 4; j++) s[i][j] = 0.0f;
#pragma unroll
        for (int d = 0; d < 64; d++) {
            float a[4], bb[4];
            *(float4*)a  = *(const float4*)&QsT[d*64 + ty*4];
            *(float4*)bb = *(const float4*)&KsT[d*64 + tx*4];
#pragma unroll
            for (int i = 0; i < 4; i++)
#pragma unroll
                for (int j = 0; j < 4; j++)
                    s[i][j] = fmaf(a[i], bb[j], s[i][j]);
        }

        if (kt == qt) {
#pragma unroll
            for (int i = 0; i < 4; i++) {
                int qg = ty*4 + i;
#pragma unroll
                for (int j = 0; j < 4; j++)
                    if (tx*4 + j > qg) s[i][j] = -INFINITY;
            }
        }

#pragma unroll
        for (int i = 0; i < 4; i++) {
            float mx = fmaxf(fmaxf(s[i][0], s[i][1]), fmaxf(s[i][2], s[i][3]));
#pragma unroll
            for (int off = 1; off < 16; off <<= 1)
                mx = fmaxf(mx, __shfl_xor_sync(0xffffffffu, mx, off));
            float mnew  = fmaxf(m_i[i], mx);
            float alpha = __expf(m_i[i] - mnew);
            m_i[i] = mnew;
            float rs = 0.0f;
#pragma unroll
            for (int j = 0; j < 4; j++) {
                s[i][j] = __expf(s[i][j] - mnew);
                rs += s[i][j];
            }
#pragma unroll
            for (int off = 1; off < 16; off <<= 1)
                rs += __shfl_xor_sync(0xffffffffu, rs, off);
            l_i[i] = l_i[i] * alpha + rs;
#pragma unroll
            for (int j = 0; j < 4; j++) o[i][j] *= alpha;
        }

#pragma unroll
        for (int j = 0; j < 4; j++) {
            *(float4*)&PsT[(tx*4 + j)*68 + ty*4] =
                make_float4(s[0][j], s[1][j], s[2][j], s[3][j]);
        }
        __syncthreads();

#pragma unroll
        for (int n = 0; n < 64; n++) {
            float a[4], bb[4];
            *(float4*)a  = *(const float4*)&PsT[n*68 + ty*4];
            *(float4*)bb = *(const float4*)&Vs[n*64 + tx*4];
#pragma unroll
            for (int i = 0; i < 4; i++)
#pragma unroll
                for (int j = 0; j < 4; j++)
                    o[i][j] = fmaf(a[i], bb[j], o[i][j]);
        }
    }

#pragma unroll
    for (int i = 0; i < 4; i++) {
        float inv = 1.0f / l_i[i];
        int t = qt*64 + ty*4 + i;
        float* dst = ctx + ((size_t)(b_ * TSEQ + t)) * DM + h*64 + tx*4;
        *(float4*)dst = make_float4(o[i][0]*inv, o[i][1]*inv,
                                    o[i][2]*inv, o[i][3]*inv);
    }
}

// ---------------------------------------------------------------------------
extern "C" void kernel_launch(void* const* d_in, const int* in_sizes, int n_in,
                              void* d_out, int out_size)
{
    const float* x  = (const float*)d_in[0];
    const float* Wq = (const float*)d_in[1];
    const float* Wk = (const float*)d_in[2];
    const float* Wv = (const float*)d_in[3];
    const float* Wo = (const float*)d_in[4];
    const float* bo = (const float*)d_in[5];
    float* out = (float*)d_out;

    float *q, *k, *v, *ctx;
    cudaGetSymbolAddress((void**)&q,   g_q);
    cudaGetSymbolAddress((void**)&k,   g_k);
    cudaGetSymbolAddress((void**)&v,   g_v);
    cudaGetSymbolAddress((void**)&ctx, g_ctx);
    __nv_bfloat16 *xh, *xl, *wh, *wl, *ch, *cl, *woh, *wol;
    cudaGetSymbolAddress((void**)&xh,  g_xh);
    cudaGetSymbolAddress((void**)&xl,  g_xl);
    cudaGetSymbolAddress((void**)&wh,  g_wh);
    cudaGetSymbolAddress((void**)&wl,  g_wl);
    cudaGetSymbolAddress((void**)&ch,  g_ch);
    cudaGetSymbolAddress((void**)&cl,  g_cl);
    cudaGetSymbolAddress((void**)&woh, g_woh);
    cudaGetSymbolAddress((void**)&wol, g_wol);

    cudaFuncSetAttribute(attn_kernel,
                         cudaFuncAttributeMaxDynamicSharedMemorySize, ATTN_SMEM);
    cudaFuncSetAttribute(mma_gemm<0>,
                         cudaFuncAttributeMaxDynamicSharedMemorySize, GEMM_SMEM);
    cudaFuncSetAttribute(mma_gemm<1>,
                         cudaFuncAttributeMaxDynamicSharedMemorySize, GEMM_SMEM);

    const int NW4 = (DM*DM)/4;
    const int NX4 = (MTOT*DM)/4;

    // splits (reference swaps names: q = x@Wk^T, k = x@Wq^T)
    split_kernel<<<NX4/256, 256>>>(x,  xh, xl, NX4);
    split_kernel<<<NW4/256, 256>>>(Wk, wh,            wl,            NW4);
    split_kernel<<<NW4/256, 256>>>(Wq, wh + DM*DM,    wl + DM*DM,    NW4);
    split_kernel<<<NW4/256, 256>>>(Wv, wh + 2*DM*DM,  wl + 2*DM*DM,  NW4);

    // fused QKV projection: N = 3072
    mma_gemm<0><<<dim3(3*DM/128, MTOT/128), 256, GEMM_SMEM>>>(
        xh, xl, wh, wl, q, k, v, nullptr, nullptr);

    attn_kernel<<<dim3(TSEQ/64, BATCH*NH), 256, ATTN_SMEM>>>(q, k, v, ctx);

    split_kernel<<<NX4/256, 256>>>(ctx, ch, cl, NX4);
    split_kernel<<<NW4/256, 256>>>(Wo,  woh, wol, NW4);

    mma_gemm<1><<<dim3(DM/128, MTOT/128), 256, GEMM_SMEM>>>(
        ch, cl, woh, wol, nullptr, nullptr, nullptr, out, bo);
}

// round 4
// speedup vs baseline: 5.4751x; 2.2312x over previous
#include <cuda_runtime.h>
#include <cuda_bf16.h>
#include <math.h>
#include <stdint.h>

#define BATCH 2
#define TSEQ  2048
#define DM    1024
#define NH    16
#define DH    64
#define MTOT  (BATCH*TSEQ)   // 4096

// ---------------- scratch (device globals; no allocation allowed) ----------
__device__ __align__(16) __nv_bfloat16 g_qh[(size_t)BATCH*NH*TSEQ*DH];
__device__ __align__(16) __nv_bfloat16 g_ql[(size_t)BATCH*NH*TSEQ*DH];
__device__ __align__(16) __nv_bfloat16 g_kh[(size_t)BATCH*NH*TSEQ*DH];
__device__ __align__(16) __nv_bfloat16 g_kl[(size_t)BATCH*NH*TSEQ*DH];
__device__ __align__(16) __nv_bfloat16 g_vh[(size_t)BATCH*NH*TSEQ*DH];
__device__ __align__(16) __nv_bfloat16 g_vl[(size_t)BATCH*NH*TSEQ*DH];

__device__ __align__(16) __nv_bfloat16 g_xh[(size_t)MTOT*DM];
__device__ __align__(16) __nv_bfloat16 g_xl[(size_t)MTOT*DM];
__device__ __align__(16) __nv_bfloat16 g_wh[(size_t)3*DM*DM];  // [Wk;Wq;Wv] (q<-Wk swap!)
__device__ __align__(16) __nv_bfloat16 g_wl[(size_t)3*DM*DM];
__device__ __align__(16) __nv_bfloat16 g_ch[(size_t)MTOT*DM];
__device__ __align__(16) __nv_bfloat16 g_cl[(size_t)MTOT*DM];
__device__ __align__(16) __nv_bfloat16 g_woh[(size_t)DM*DM];
__device__ __align__(16) __nv_bfloat16 g_wol[(size_t)DM*DM];

// ---------------- helpers ---------------------------------------------------
__device__ __forceinline__ uint32_t smem_u32(const void* p) {
    uint32_t a;
    asm("{ .reg .u64 t; cvta.to.shared.u64 t, %1; cvt.u32.u64 %0, t; }"
        : "=r"(a) : "l"(p));
    return a;
}
__device__ __forceinline__ void cp_async16(uint32_t dst, const void* src) {
    asm volatile("cp.async.cg.shared.global [%0], [%1], 16;"
                 :: "r"(dst), "l"(src) : "memory");
}
__device__ __forceinline__ void cp_commit() {
    asm volatile("cp.async.commit_group;" ::: "memory");
}
__device__ __forceinline__ void cp_wait_all() {
    asm volatile("cp.async.wait_group 0;" ::: "memory");
}
__device__ __forceinline__ void ldsm4(uint32_t* r, uint32_t a) {
    asm volatile("ldmatrix.sync.aligned.m8n8.x4.shared.b16 {%0,%1,%2,%3}, [%4];"
                 : "=r"(r[0]), "=r"(r[1]), "=r"(r[2]), "=r"(r[3]) : "r"(a));
}
__device__ __forceinline__ void ldsm4t(uint32_t* r, uint32_t a) {
    asm volatile("ldmatrix.sync.aligned.m8n8.x4.trans.shared.b16 {%0,%1,%2,%3}, [%4];"
                 : "=r"(r[0]), "=r"(r[1]), "=r"(r[2]), "=r"(r[3]) : "r"(a));
}
__device__ __forceinline__ void mma_bf16(float* c, const uint32_t* a, const uint32_t* b) {
    asm volatile(
        "mma.sync.aligned.m16n8k16.row.col.f32.bf16.bf16.f32 "
        "{%0,%1,%2,%3}, {%4,%5,%6,%7}, {%8,%9}, {%0,%1,%2,%3};"
        : "+f"(c[0]), "+f"(c[1]), "+f"(c[2]), "+f"(c[3])
        : "r"(a[0]), "r"(a[1]), "r"(a[2]), "r"(a[3]), "r"(b[0]), "r"(b[1]));
}
// pack two fp32 -> bf16x2 (lo half = v0)
__device__ __forceinline__ uint32_t cvt2(float v_hi, float v_lo) {
    uint32_t r;
    asm("cvt.rn.bf16x2.f32 %0, %1, %2;" : "=r"(r) : "f"(v_hi), "f"(v_lo));
    return r;
}
// split (v0,v1) into bf16x2 hi part + bf16x2 residual
__device__ __forceinline__ void split2(float v0, float v1, uint32_t& hi, uint32_t& lo) {
    hi = cvt2(v1, v0);
    float h0 = __uint_as_float(hi << 16);
    float h1 = __uint_as_float(hi & 0xffff0000u);
    lo = cvt2(v1 - h1, v0 - h0);
}
// SW128 swizzle on (row,colb): row stride 128B
__device__ __forceinline__ uint32_t swz(int row, int colb) {
    uint32_t off = row * 128 + colb;
    return off ^ ((off >> 3) & 0x70);
}

// ---------------- fp32 -> bf16 hi/lo split ----------------------------------
__global__ void __launch_bounds__(256) split_kernel(
    const float* __restrict__ in, __nv_bfloat16* __restrict__ hi,
    __nv_bfloat16* __restrict__ lo, int n4)
{
    int i = blockIdx.x * 256 + threadIdx.x;
    if (i >= n4) return;
    float4 v = ((const float4*)in)[i];
    __nv_bfloat16 h[4], l[4];
    float f[4] = {v.x, v.y, v.z, v.w};
#pragma unroll
    for (int j = 0; j < 4; j++) {
        h[j] = __float2bfloat16(f[j]);
        l[j] = __float2bfloat16(f[j] - __bfloat162float(h[j]));
    }
    *(uint2*)(hi + (size_t)i*4) = *(uint2*)h;
    *(uint2*)(lo + (size_t)i*4) = *(uint2*)l;
}

// ---------------------------------------------------------------------------
// Split-bf16 GEMM on HMMA. MODE 0: fused QKV, writes bf16 hi/lo head-major
// (scale 1/8 folded into q). MODE 1: fp32 out + bias.
// ---------------------------------------------------------------------------
#define GK       DM
#define BK       64
#define NCHUNK   (GK/BK)        // 16
#define TILE_B   (128*128)
#define BUF_B    (4*TILE_B)
#define GEMM_SMEM (2*BUF_B)     // 131072

template<int MODE>
__global__ void __launch_bounds__(256, 1) mma_gemm(
    const __nv_bfloat16* __restrict__ Ah, const __nv_bfloat16* __restrict__ Al,
    const __nv_bfloat16* __restrict__ Bh, const __nv_bfloat16* __restrict__ Bl,
    __nv_bfloat16* __restrict__ qh, __nv_bfloat16* __restrict__ ql,
    __nv_bfloat16* __restrict__ kh, __nv_bfloat16* __restrict__ kl,
    __nv_bfloat16* __restrict__ vh, __nv_bfloat16* __restrict__ vl,
    float* __restrict__ out, const float* __restrict__ bias)
{
    extern __shared__ char smem[];
    const uint32_t sb = smem_u32(smem);
    const int tid  = threadIdx.x;
    const int lane = tid & 31;
    const int w    = tid >> 5;
    const int m0   = blockIdx.y * 128;
    const int n0   = blockIdx.x * 128;

    const __nv_bfloat16* srcs[4] = {Ah + (size_t)m0*GK, Al + (size_t)m0*GK,
                                    Bh + (size_t)n0*GK, Bl + (size_t)n0*GK};

    auto issue_chunk = [&](int buf, int k0) {
        uint32_t dbase = sb + buf * BUF_B;
#pragma unroll
        for (int t = 0; t < 4; t++) {
            const __nv_bfloat16* src = srcs[t] + k0;
            uint32_t tb = dbase + t * TILE_B;
#pragma unroll
            for (int r2 = 0; r2 < 4; r2++) {
                int id  = tid + 256 * r2;
                int row = id >> 3;
                int c16 = id & 7;
                cp_async16(tb + swz(row, c16 * 16), src + (size_t)row*GK + c16*8);
            }
        }
        cp_commit();
    };

    float acc[2][8][4];
#pragma unroll
    for (int mt = 0; mt < 2; mt++)
#pragma unroll
        for (int nt = 0; nt < 8; nt++)
#pragma unroll
            for (int e = 0; e < 4; e++) acc[mt][nt][e] = 0.0f;

    const int mr  = (w & 3) * 32;
    const int nc0 = (w >> 2) * 64;
    const int quad = lane >> 3;
    const int l7   = lane & 7;
    const int a_row_off = (quad & 1) * 8 + l7;
    const int a_col_off = (quad >> 1) * 16;
    const int b_row_off = (quad >> 1) * 8 + l7;
    const int b_col_off = (quad & 1) * 16;

    issue_chunk(0, 0);

    for (int c = 0; c < NCHUNK; c++) {
        const int b = c & 1;
        cp_wait_all();
        __syncthreads();
        if (c + 1 < NCHUNK) issue_chunk(b ^ 1, (c + 1) * BK);

        const uint32_t pAh = sb + b*BUF_B;
        const uint32_t pAl = pAh + TILE_B;
        const uint32_t pBh = pAh + 2*TILE_B;
        const uint32_t pBl = pAh + 3*TILE_B;

#pragma unroll
        for (int ks = 0; ks < 4; ks++) {
            const int k0b = ks * 32;
            uint32_t aH[2][4], aL[2][4], bF[8][2];
#pragma unroll
            for (int mt = 0; mt < 2; mt++) {
                int row = mr + mt*16 + a_row_off;
                ldsm4(aH[mt], pAh + swz(row, k0b + a_col_off));
                ldsm4(aL[mt], pAl + swz(row, k0b + a_col_off));
            }
#pragma unroll
            for (int ng = 0; ng < 4; ng++) {
                uint32_t t4[4];
                ldsm4(t4, pBh + swz(nc0 + ng*16 + b_row_off, k0b + b_col_off));
                bF[ng*2][0] = t4[0]; bF[ng*2][1] = t4[1];
                bF[ng*2+1][0] = t4[2]; bF[ng*2+1][1] = t4[3];
            }
#pragma unroll
            for (int mt = 0; mt < 2; mt++)
#pragma unroll
                for (int nt = 0; nt < 8; nt++) mma_bf16(acc[mt][nt], aH[mt], bF[nt]);
#pragma unroll
            for (int mt = 0; mt < 2; mt++)
#pragma unroll
                for (int nt = 0; nt < 8; nt++) mma_bf16(acc[mt][nt], aL[mt], bF[nt]);
#pragma unroll
            for (int ng = 0; ng < 4; ng++) {
                uint32_t t4[4];
                ldsm4(t4, pBl + swz(nc0 + ng*16 + b_row_off, k0b + b_col_off));
                bF[ng*2][0] = t4[0]; bF[ng*2][1] = t4[1];
                bF[ng*2+1][0] = t4[2]; bF[ng*2+1][1] = t4[3];
            }
#pragma unroll
            for (int mt = 0; mt < 2; mt++)
#pragma unroll
                for (int nt = 0; nt < 8; nt++) mma_bf16(acc[mt][nt], aH[mt], bF[nt]);
        }
        __syncthreads();
    }

    // ---- epilogue ----
#pragma unroll
    for (int mt = 0; mt < 2; mt++) {
#pragma unroll
        for (int half = 0; half < 2; half++) {
            const int m = m0 + mr + mt*16 + (lane >> 2) + half*8;
#pragma unroll
            for (int nt = 0; nt < 8; nt++) {
                const int n = n0 + nc0 + nt*8 + (lane & 3)*2;
                const float c0 = acc[mt][nt][half*2 + 0];
                const float c1 = acc[mt][nt][half*2 + 1];
                if (MODE == 0) {
                    const int bb  = m >> 11;
                    const int t   = m & 2047;
                    const int mat = n >> 10;
                    const int np  = n & 1023;
                    const float sc = (mat == 0) ? 0.125f : 1.0f;  // softmax scale into q
                    uint32_t hi, lo;
                    split2(c0*sc, c1*sc, hi, lo);
                    __nv_bfloat16* ph = (mat == 0) ? qh : ((mat == 1) ? kh : vh);
                    __nv_bfloat16* pl = (mat == 0) ? ql : ((mat == 1) ? kl : vl);
                    size_t idx = ((size_t)(bb*NH + (np >> 6)) * TSEQ + t) * DH + (np & 63);
                    *(uint32_t*)(ph + idx) = hi;
                    *(uint32_t*)(pl + idx) = lo;
                } else {
                    float* p = out + (size_t)m * DM + n;
                    p[0] = c0 + __ldg(bias + n);
                    p[1] = c1 + __ldg(bias + n + 1);
                }
            }
        }
    }
}

// ---------------------------------------------------------------------------
// Causal flash attention on HMMA, split-bf16.
// Block: 128 queries, 8 warps (16 rows each), 64-key chunks, cp.async DB.
// Writes ctx directly as bf16 hi/lo (ch/cl) in [m][1024] layout.
// ---------------------------------------------------------------------------
#define AKV   8192               // one 64x64 bf16 matrix (64 rows * 128B)
#define ABUF  (4*AKV)            // Kh,Kl,Vh,Vl
#define AQ_OFF (2*ABUF)
#define ATTN_SMEM (2*ABUF + 2*16384)   // 98304

__global__ void __launch_bounds__(256, 1) attn_mma(
    const __nv_bfloat16* __restrict__ qh_g, const __nv_bfloat16* __restrict__ ql_g,
    const __nv_bfloat16* __restrict__ kh_g, const __nv_bfloat16* __restrict__ kl_g,
    const __nv_bfloat16* __restrict__ vh_g, const __nv_bfloat16* __restrict__ vl_g,
    __nv_bfloat16* __restrict__ ch_g, __nv_bfloat16* __restrict__ cl_g)
{
    extern __shared__ char smem[];
    const uint32_t sb = smem_u32(smem);
    const int tid  = threadIdx.x;
    const int lane = tid & 31;
    const int w    = tid >> 5;
    const int qt   = blockIdx.x;     // 0..15
    const int bh   = blockIdx.y;     // 0..31
    const int g    = lane >> 2;
    const int tig  = lane & 3;
    const int quad = lane >> 3;
    const int l7   = lane & 7;
    const int a_row  = (quad & 1) * 8 + l7;
    const int a_colb = (quad >> 1) * 16;
    const int b_row  = (quad >> 1) * 8 + l7;
    const int b_colb = (quad & 1) * 16;
    const int v_row  = (quad & 1) * 8 + l7;   // trans: rows = keys
    const int v_colb = (quad >> 1) * 16;

    const size_t base = (size_t)bh * TSEQ * DH;
    const int rowbase = qt * 128 + w * 16;

    auto issue_kv = [&](int buf, int key0) {
        uint32_t db = sb + buf * ABUF;
        const __nv_bfloat16* srcs[4] = {kh_g, kl_g, vh_g, vl_g};
#pragma unroll
        for (int t4 = 0; t4 < 4; t4++) {
#pragma unroll
            for (int r = 0; r < 2; r++) {
                int id  = tid + 256 * r;
                int row = id >> 3;
                int c16 = id & 7;
                cp_async16(db + t4*AKV + swz(row, c16*16),
                           srcs[t4] + base + (size_t)(key0 + row)*DH + c16*8);
            }
        }
    };

    // prologue: Q tile + chunk 0
#pragma unroll
    for (int r = 0; r < 4; r++) {
        int id  = tid + 256 * r;
        int row = id >> 3;              // 0..127
        int c16 = id & 7;
        cp_async16(sb + AQ_OFF         + swz(row, c16*16),
                   qh_g + base + (size_t)(qt*128 + row)*DH + c16*8);
        cp_async16(sb + AQ_OFF + 16384 + swz(row, c16*16),
                   ql_g + base + (size_t)(qt*128 + row)*DH + c16*8);
    }
    issue_kv(0, 0);
    cp_commit();

    float s[8][4], o[8][4];
    float m_i[2] = {-1e30f, -1e30f}, l_i[2] = {0.0f, 0.0f};
#pragma unroll
    for (int nt = 0; nt < 8; nt++)
#pragma unroll
        for (int e = 0; e < 4; e++) o[nt][e] = 0.0f;
    uint32_t qfh[4][4], qfl[4][4];

    const int NKT = 2*qt + 2;
    for (int c = 0; c < NKT; c++) {
        cp_wait_all();
        __syncthreads();
        if (c == 0) {
#pragma unroll
            for (int ks = 0; ks < 4; ks++) {
                ldsm4(qfh[ks], sb + AQ_OFF         + swz(w*16 + a_row, ks*32 + a_colb));
                ldsm4(qfl[ks], sb + AQ_OFF + 16384 + swz(w*16 + a_row, ks*32 + a_colb));
            }
        }
        if (c + 1 < NKT) { issue_kv((c + 1) & 1, (c + 1) * 64); cp_commit(); }

        const int key0 = c * 64;
        if (key0 <= rowbase + 15) {          // warp has unmasked work
            const uint32_t pb = sb + (c & 1) * ABUF;

            // ---- S = Qh*Kh + Ql*Kh + Qh*Kl ----
#pragma unroll
            for (int nt = 0; nt < 8; nt++)
#pragma unroll
                for (int e = 0; e < 4; e++) s[nt][e] = 0.0f;
#pragma unroll
            for (int ks = 0; ks < 4; ks++) {
                uint32_t bK[8][2], t4[4];
#pragma unroll
                for (int ng = 0; ng < 4; ng++) {
                    ldsm4(t4, pb + swz(ng*16 + b_row, ks*32 + b_colb));   // Kh
                    bK[ng*2][0] = t4[0]; bK[ng*2][1] = t4[1];
                    bK[ng*2+1][0] = t4[2]; bK[ng*2+1][1] = t4[3];
                }
#pragma unroll
                for (int nt = 0; nt < 8; nt++) mma_bf16(s[nt], qfh[ks], bK[nt]);
#pragma unroll
                for (int nt = 0; nt < 8; nt++) mma_bf16(s[nt], qfl[ks], bK[nt]);
#pragma unroll
                for (int ng = 0; ng < 4; ng++) {
                    ldsm4(t4, pb + AKV + swz(ng*16 + b_row, ks*32 + b_colb)); // Kl
                    bK[ng*2][0] = t4[0]; bK[ng*2][1] = t4[1];
                    bK[ng*2+1][0] = t4[2]; bK[ng*2+1][1] = t4[3];
                }
#pragma unroll
                for (int nt = 0; nt < 8; nt++) mma_bf16(s[nt], qfh[ks], bK[nt]);
            }

            // ---- causal mask (diagonal-ish chunks only) ----
            if (key0 + 63 > rowbase) {
#pragma unroll
                for (int nt = 0; nt < 8; nt++) {
#pragma unroll
                    for (int e = 0; e < 4; e++) {
                        int col = key0 + nt*8 + 2*tig + (e & 1);
                        int row = rowbase + g + ((e >= 2) ? 8 : 0);
                        if (col > row) s[nt][e] = -1e30f;
                    }
                }
            }

            // ---- online softmax ----
            float rm0 = -1e30f, rm1 = -1e30f;
#pragma unroll
            for (int nt = 0; nt < 8; nt++) {
                rm0 = fmaxf(rm0, fmaxf(s[nt][0], s[nt][1]));
                rm1 = fmaxf(rm1, fmaxf(s[nt][2], s[nt][3]));
            }
            rm0 = fmaxf(rm0, __shfl_xor_sync(0xffffffffu, rm0, 1));
            rm0 = fmaxf(rm0, __shfl_xor_sync(0xffffffffu, rm0, 2));
            rm1 = fmaxf(rm1, __shfl_xor_sync(0xffffffffu, rm1, 1));
            rm1 = fmaxf(rm1, __shfl_xor_sync(0xffffffffu, rm1, 2));
            float mn0 = fmaxf(m_i[0], rm0), mn1 = fmaxf(m_i[1], rm1);
            float al0 = __expf(m_i[0] - mn0), al1 = __expf(m_i[1] - mn1);
            m_i[0] = mn0; m_i[1] = mn1;
            float rs0 = 0.0f, rs1 = 0.0f;
#pragma unroll
            for (int nt = 0; nt < 8; nt++) {
                s[nt][0] = __expf(s[nt][0] - mn0);
                s[nt][1] = __expf(s[nt][1] - mn0);
                s[nt][2] = __expf(s[nt][2] - mn1);
                s[nt][3] = __expf(s[nt][3] - mn1);
                rs0 += s[nt][0] + s[nt][1];
                rs1 += s[nt][2] + s[nt][3];
            }
            rs0 += __shfl_xor_sync(0xffffffffu, rs0, 1);
            rs0 += __shfl_xor_sync(0xffffffffu, rs0, 2);
            rs1 += __shfl_xor_sync(0xffffffffu, rs1, 1);
            rs1 += __shfl_xor_sync(0xffffffffu, rs1, 2);
            l_i[0] = l_i[0]*al0 + rs0;
            l_i[1] = l_i[1]*al1 + rs1;
#pragma unroll
            for (int nt = 0; nt < 8; nt++) {
                o[nt][0] *= al0; o[nt][1] *= al0;
                o[nt][2] *= al1; o[nt][3] *= al1;
            }

            // ---- O += Ph*Vh + Pl*Vh + Ph*Vl ----
#pragma unroll
            for (int ks = 0; ks < 4; ks++) {
                uint32_t ph[4], pl[4];
                split2(s[2*ks][0],   s[2*ks][1],   ph[0], pl[0]);
                split2(s[2*ks][2],   s[2*ks][3],   ph[1], pl[1]);
                split2(s[2*ks+1][0], s[2*ks+1][1], ph[2], pl[2]);
                split2(s[2*ks+1][2], s[2*ks+1][3], ph[3], pl[3]);
                uint32_t bV[8][2], t4[4];
#pragma unroll
                for (int ng = 0; ng < 4; ng++) {
                    ldsm4t(t4, pb + 2*AKV + swz(ks*16 + v_row, ng*32 + v_colb)); // Vh
                    bV[ng*2][0] = t4[0]; bV[ng*2][1] = t4[1];
                    bV[ng*2+1][0] = t4[2]; bV[ng*2+1][1] = t4[3];
                }
#pragma unroll
                for (int nt = 0; nt < 8; nt++) mma_bf16(o[nt], ph, bV[nt]);
#pragma unroll
                for (int nt = 0; nt < 8; nt++) mma_bf16(o[nt], pl, bV[nt]);
#pragma unroll
                for (int ng = 0; ng < 4; ng++) {
                    ldsm4t(t4, pb + 3*AKV + swz(ks*16 + v_row, ng*32 + v_colb)); // Vl
                    bV[ng*2][0] = t4[0]; bV[ng*2][1] = t4[1];
                    bV[ng*2+1][0] = t4[2]; bV[ng*2+1][1] = t4[3];
                }
#pragma unroll
                for (int nt = 0; nt < 8; nt++) mma_bf16(o[nt], ph, bV[nt]);
            }
        }
    }

    // ---- epilogue: ctx as bf16 hi/lo into ch/cl [m][1024] ----
    const int b_ = bh >> 4;
    const int h  = bh & 15;
    const float inv0 = 1.0f / l_i[0];
    const float inv1 = 1.0f / l_i[1];
    const int t0r = rowbase + g;
    const int t1r = rowbase + g + 8;
#pragma unroll
    for (int nt = 0; nt < 8; nt++) {
        const int col = h*64 + nt*8 + 2*tig;
        uint32_t hi, lo;
        split2(o[nt][0]*inv0, o[nt][1]*inv0, hi, lo);
        size_t i0 = ((size_t)(b_*TSEQ) + t0r) * DM + col;
        *(uint32_t*)(ch_g + i0) = hi;
        *(uint32_t*)(cl_g + i0) = lo;
        split2(o[nt][2]*inv1, o[nt][3]*inv1, hi, lo);
        size_t i1 = ((size_t)(b_*TSEQ) + t1r) * DM + col;
        *(uint32_t*)(ch_g + i1) = hi;
        *(uint32_t*)(cl_g + i1) = lo;
    }
}

// ---------------------------------------------------------------------------
extern "C" void kernel_launch(void* const* d_in, const int* in_sizes, int n_in,
                              void* d_out, int out_size)
{
    const float* x  = (const float*)d_in[0];
    const float* Wq = (const float*)d_in[1];
    const float* Wk = (const float*)d_in[2];
    const float* Wv = (const float*)d_in[3];
    const float* Wo = (const float*)d_in[4];
    const float* bo = (const float*)d_in[5];
    float* out = (float*)d_out;

    __nv_bfloat16 *qh, *ql, *kh, *kl, *vh, *vl;
    __nv_bfloat16 *xh, *xl, *wh, *wl, *ch, *cl, *woh, *wol;
    cudaGetSymbolAddress((void**)&qh,  g_qh);
    cudaGetSymbolAddress((void**)&ql,  g_ql);
    cudaGetSymbolAddress((void**)&kh,  g_kh);
    cudaGetSymbolAddress((void**)&kl,  g_kl);
    cudaGetSymbolAddress((void**)&vh,  g_vh);
    cudaGetSymbolAddress((void**)&vl,  g_vl);
    cudaGetSymbolAddress((void**)&xh,  g_xh);
    cudaGetSymbolAddress((void**)&xl,  g_xl);
    cudaGetSymbolAddress((void**)&wh,  g_wh);
    cudaGetSymbolAddress((void**)&wl,  g_wl);
    cudaGetSymbolAddress((void**)&ch,  g_ch);
    cudaGetSymbolAddress((void**)&cl,  g_cl);
    cudaGetSymbolAddress((void**)&woh, g_woh);
    cudaGetSymbolAddress((void**)&wol, g_wol);

    cudaFuncSetAttribute(mma_gemm<0>,
                         cudaFuncAttributeMaxDynamicSharedMemorySize, GEMM_SMEM);
    cudaFuncSetAttribute(mma_gemm<1>,
                         cudaFuncAttributeMaxDynamicSharedMemorySize, GEMM_SMEM);
    cudaFuncSetAttribute(attn_mma,
                         cudaFuncAttributeMaxDynamicSharedMemorySize, ATTN_SMEM);

    const int NW4 = (DM*DM)/4;
    const int NX4 = (MTOT*DM)/4;

    // splits (reference swaps names: q = x@Wk^T, k = x@Wq^T)
    split_kernel<<<NX4/256, 256>>>(x,  xh, xl, NX4);
    split_kernel<<<NW4/256, 256>>>(Wk, wh,            wl,            NW4);
    split_kernel<<<NW4/256, 256>>>(Wq, wh + DM*DM,    wl + DM*DM,    NW4);
    split_kernel<<<NW4/256, 256>>>(Wv, wh + 2*DM*DM,  wl + 2*DM*DM,  NW4);
    split_kernel<<<NW4/256, 256>>>(Wo, woh, wol, NW4);

    // fused QKV projection (N=3072), bf16 hi/lo epilogue
    mma_gemm<0><<<dim3(3*DM/128, MTOT/128), 256, GEMM_SMEM>>>(
        xh, xl, wh, wl, qh, ql, kh, kl, vh, vl, nullptr, nullptr);

    attn_mma<<<dim3(TSEQ/128, BATCH*NH), 256, ATTN_SMEM>>>(
        qh, ql, kh, kl, vh, vl, ch, cl);

    mma_gemm<1><<<dim3(DM/128, MTOT/128), 256, GEMM_SMEM>>>(
        ch, cl, woh, wol, nullptr, nullptr, nullptr, nullptr, nullptr, nullptr,
        out, bo);
}